// round 1
// baseline (speedup 1.0000x reference)
#include <cuda_runtime.h>
#include <cuda_bf16.h>

// Problem constants (fixed by setup_inputs): length=8192, n=4096.
#define ENC_LEN 8192
#define ENC_VEC4 (ENC_LEN / 4)   // 2048 float4 per row

// Scratch for the computed encoding row (allocation-free per harness rules).
__device__ float g_enc[ENC_LEN];

// ---------------------------------------------------------------------------
// Phase 1: compute enc[i] once, in double precision for robustness vs
// fast-math sinf on large arguments (angle can reach ~1000 rad).
//   even i: sin(pos * 1000^(-i/length))
//   odd  i: cos(pos * 1000^(-(i-1)/length))
// ---------------------------------------------------------------------------
__global__ void compute_enc_kernel(const float* __restrict__ position, int length) {
    int i = blockIdx.x * blockDim.x + threadIdx.x;
    if (i >= length) return;
    double pos = (double)position[0];
    int base = i & ~1;                       // i for even, i-1 for odd
    double expo = (double)base / (double)length;
    // 1000^(-expo) = exp(-expo * ln(1000))
    double inv_freq = exp(-expo * 6.907755278982137);  // ln(1000)
    double angle = pos * inv_freq;
    double v = (i & 1) ? cos(angle) : sin(angle);
    g_enc[i] = (float)v;
}

// ---------------------------------------------------------------------------
// Phase 2: broadcast enc row to all n rows. Each CTA of 512 threads caches the
// whole 8192-float row in registers (4 x float4 per thread), then streams it
// to its assigned rows with coalesced float4 stores. Pure HBM-write-bound.
// ---------------------------------------------------------------------------
__global__ void __launch_bounds__(512, 4)
broadcast_kernel(float4* __restrict__ out, int n) {
    const int tid = threadIdx.x;

    // Load the full row into registers: thread t owns float4 indices
    // t, t+512, t+1024, t+1536  (512*4 = 2048 = ENC_VEC4).
    const float4* __restrict__ enc4 = reinterpret_cast<const float4*>(g_enc);
    float4 v0 = enc4[tid];
    float4 v1 = enc4[tid + 512];
    float4 v2 = enc4[tid + 1024];
    float4 v3 = enc4[tid + 1536];

    for (int row = blockIdx.x; row < n; row += gridDim.x) {
        float4* __restrict__ dst = out + (size_t)row * ENC_VEC4;
        dst[tid]        = v0;
        dst[tid + 512]  = v1;
        dst[tid + 1024] = v2;
        dst[tid + 1536] = v3;
    }
}

extern "C" void kernel_launch(void* const* d_in, const int* in_sizes, int n_in,
                              void* d_out, int out_size) {
    // Inputs per metadata order: length (int scalar), n (int scalar),
    // position (float[1]). We take the float pointer; sizes are fixed.
    const float* position = nullptr;
    // position is the last input; scan for robustness (ints vs float layout).
    // setup_inputs order: length, n, position -> index 2.
    position = (const float*)d_in[n_in - 1];

    const int length = ENC_LEN;
    const int n = out_size / length;         // 4096

    compute_enc_kernel<<<(length + 511) / 512, 512>>>(position, length);

    // 148 SMs * 4 CTAs/SM = 592 persistent-ish blocks.
    int grid = 592;
    if (grid > n) grid = n;
    broadcast_kernel<<<grid, 512>>>((float4*)d_out, n);
}

// round 2
// speedup vs baseline: 1.3921x; 1.3921x over previous
#include <cuda_runtime.h>
#include <cuda_bf16.h>

// Problem constants (fixed by setup_inputs): length=8192, n=4096.
#define ENC_LEN   8192
#define ENC_VEC4  (ENC_LEN / 4)   // 2048 float4 per row
#define BLOCK     512

// inv_freq(base) = 1000^(-base/8192) = exp2(-(base/8192) * log2(1000))
// Compensated fp32 product keeps the exp2 argument accurate to ~1 ulp.
__device__ __forceinline__ float inv_freq(int base) {
    const double Ld = 9.965784284662087;          // log2(1000)
    const float  Lh = (float)Ld;
    const float  Ll = (float)(Ld - (double)Lh);   // low-order correction
    float e   = (float)base * (1.0f / 8192.0f);   // exact (base < 2^13)
    float p   = e * Lh;
    float err = fmaf(e, Lh, -p);                  // exact residual of e*Lh
    float t   = p + fmaf(e, Ll, err);             // ≈ e * log2(1000)
    return exp2f(-t);
}

// ---------------------------------------------------------------------------
// Fused kernel: each thread computes its 16 enc values (4 float4, 8 angles)
// in registers, then streams them to its assigned rows with coalesced 16B
// stores. Compute prologue (~1us) amortizes over ~14 row writes per CTA;
// runtime is pure HBM-write-bound.
//
// float4 layout: enc4[j] covers elements {4j, 4j+1, 4j+2, 4j+3}
//   = { sin(a0), cos(a0), sin(a1), cos(a1) }  with a0 from base 4j,
//     a1 from base 4j+2.
// ---------------------------------------------------------------------------
__global__ void __launch_bounds__(BLOCK, 2)
sinusoidal_fused_kernel(const float* __restrict__ position,
                        float4* __restrict__ out, int n) {
    const int tid = threadIdx.x;
    const float pos = position[0];

    float4 v[4];
#pragma unroll
    for (int k = 0; k < 4; ++k) {
        int j = tid + k * BLOCK;          // float4 index within the row
        float a0 = pos * inv_freq(4 * j);
        float a1 = pos * inv_freq(4 * j + 2);
        float s0, c0, s1, c1;
        sincosf(a0, &s0, &c0);
        sincosf(a1, &s1, &c1);
        v[k] = make_float4(s0, c0, s1, c1);
    }

    for (int row = blockIdx.x; row < n; row += gridDim.x) {
        float4* __restrict__ dst = out + (size_t)row * ENC_VEC4;
        dst[tid]              = v[0];
        dst[tid + BLOCK]      = v[1];
        dst[tid + 2 * BLOCK]  = v[2];
        dst[tid + 3 * BLOCK]  = v[3];
    }
}

extern "C" void kernel_launch(void* const* d_in, const int* in_sizes, int n_in,
                              void* d_out, int out_size) {
    // setup_inputs order: length (scalar), n (scalar), position (float[1]).
    const float* position = (const float*)d_in[n_in - 1];

    const int n = out_size / ENC_LEN;     // 4096

    // 2 CTAs per SM (148 SMs) -> 296 CTAs; each writes ~14 rows.
    int grid = 296;
    if (grid > n) grid = n;
    sinusoidal_fused_kernel<<<grid, BLOCK>>>(position, (float4*)d_out, n);
}

// round 3
// speedup vs baseline: 1.4124x; 1.0146x over previous
#include <cuda_runtime.h>
#include <cuda_bf16.h>

// Problem constants (fixed by setup_inputs): length=8192, n=4096.
#define ENC_LEN   8192
#define ENC_VEC4  (ENC_LEN / 4)   // 2048 float4 per row
#define BLOCK     512

// inv_freq(base) = 1000^(-base/8192) = exp2(-(base/8192) * log2(1000))
// Compensated fp32 product keeps the exp2 argument accurate to ~1 ulp.
__device__ __forceinline__ float inv_freq(int base) {
    const double Ld = 9.965784284662087;          // log2(1000)
    const float  Lh = (float)Ld;
    const float  Ll = (float)(Ld - (double)Lh);   // low-order correction
    float e   = (float)base * (1.0f / 8192.0f);   // exact (base < 2^13)
    float p   = e * Lh;
    float err = fmaf(e, Lh, -p);                  // exact residual of e*Lh
    float t   = p + fmaf(e, Ll, err);             // ≈ e * log2(1000)
    return exp2f(-t);
}

// Streaming 16B store: evict-first L2 policy so dirty output lines drain to
// DRAM eagerly instead of piling up and serializing with the next replay.
__device__ __forceinline__ void stcs4(float4* p, float4 v) {
    asm volatile("st.global.cs.v4.f32 [%0], {%1, %2, %3, %4};"
                 :: "l"(p), "f"(v.x), "f"(v.y), "f"(v.z), "f"(v.w)
                 : "memory");
}

// ---------------------------------------------------------------------------
// Fused kernel: each thread computes its 16 enc values (4 float4, 8 angles)
// in registers, then streams them to its assigned rows. 2-row unroll keeps
// 8 independent STG.128 in flight per warp per iteration.
// ---------------------------------------------------------------------------
__global__ void __launch_bounds__(BLOCK)
sinusoidal_fused_kernel(const float* __restrict__ position,
                        float4* __restrict__ out, int n) {
    const int tid = threadIdx.x;
    const float pos = position[0];

    float4 v[4];
#pragma unroll
    for (int k = 0; k < 4; ++k) {
        int j = tid + k * BLOCK;          // float4 index within the row
        float a0 = pos * inv_freq(4 * j);
        float a1 = pos * inv_freq(4 * j + 2);
        float s0, c0, s1, c1;
        sincosf(a0, &s0, &c0);
        sincosf(a1, &s1, &c1);
        v[k] = make_float4(s0, c0, s1, c1);
    }

    // 2-row unrolled streaming loop.
    int row = blockIdx.x * 2;
    const int stride = gridDim.x * 2;
    for (; row + 1 < n; row += stride) {
        float4* __restrict__ d0 = out + (size_t)row * ENC_VEC4;
        float4* __restrict__ d1 = d0 + ENC_VEC4;
#pragma unroll
        for (int k = 0; k < 4; ++k) stcs4(d0 + tid + k * BLOCK, v[k]);
#pragma unroll
        for (int k = 0; k < 4; ++k) stcs4(d1 + tid + k * BLOCK, v[k]);
    }
    if (row < n) {
        float4* __restrict__ d0 = out + (size_t)row * ENC_VEC4;
#pragma unroll
        for (int k = 0; k < 4; ++k) stcs4(d0 + tid + k * BLOCK, v[k]);
    }
}

extern "C" void kernel_launch(void* const* d_in, const int* in_sizes, int n_in,
                              void* d_out, int out_size) {
    // setup_inputs order: length (scalar), n (scalar), position (float[1]).
    const float* position = (const float*)d_in[n_in - 1];

    const int n = out_size / ENC_LEN;     // 4096

    // Up to 4 CTAs/SM (148 SMs) -> 592 CTAs; each writes ~7 row-pairs.
    int grid = 592;
    if (grid * 2 > n) grid = (n + 1) / 2;
    sinusoidal_fused_kernel<<<grid, BLOCK>>>(position, (float4*)d_out, n);
}